// round 13
// baseline (speedup 1.0000x reference)
#include <cuda_runtime.h>
#include <cuda_fp16.h>
#include <cstdint>

#define BB 64
#define TT 1024
#define II 256
#define HH 512
#define G4 2048
#define NCTA 128          // persistent CTAs; CTA p owns h-cols [4p,4p+4)
#define NC 16             // gate columns per CTA (4 h-cols x 4 gates)
#define VT2 520           // V smem stride in halves (word stride 260 == 4 mod 32)
#define HS2 520           // h smem stride in halves
#define GS_S 18
#define REC_SMEM_BYTES (NC*VT2*2 + 64*HS2*2 + 2*64*GS_S*4)

// -------- global scratch (static device memory; no runtime allocation) -----
__device__ float  g_xproj[(size_t)BB * TT * G4];  // [t*64+b][2048], bias folded
__device__ __half g_hbuf[2][BB * HH];             // h ping-pong, fp16
__device__ int    g_cnt;                          // monotonic arrival counter

// -------- helpers -----------------------------------------------------------
__device__ __forceinline__ float tf32r(float f) {
    unsigned u; asm("cvt.rna.tf32.f32 %0, %1;" : "=r"(u) : "f"(f));
    return __uint_as_float(u);
}
__device__ __forceinline__ unsigned fb(float f) { return __float_as_uint(f); }

__device__ __forceinline__ void mma_tf32(float* c,
    unsigned a0, unsigned a1, unsigned a2, unsigned a3, unsigned b0, unsigned b1) {
    asm volatile(
        "mma.sync.aligned.m16n8k8.row.col.f32.tf32.tf32.f32 "
        "{%0,%1,%2,%3},{%4,%5,%6,%7},{%8,%9},{%0,%1,%2,%3};"
        : "+f"(c[0]), "+f"(c[1]), "+f"(c[2]), "+f"(c[3])
        : "r"(a0), "r"(a1), "r"(a2), "r"(a3), "r"(b0), "r"(b1));
}
__device__ __forceinline__ void mma_f16(float* c,
    unsigned a0, unsigned a1, unsigned a2, unsigned a3, unsigned b0, unsigned b1) {
    asm volatile(
        "mma.sync.aligned.m16n8k16.row.col.f32.f16.f16.f32 "
        "{%0,%1,%2,%3},{%4,%5,%6,%7},{%8,%9},{%0,%1,%2,%3};"
        : "+f"(c[0]), "+f"(c[1]), "+f"(c[2]), "+f"(c[3])
        : "r"(a0), "r"(a1), "r"(a2), "r"(a3), "r"(b0), "r"(b1));
}
__device__ __forceinline__ int ld_acq(const int* p) {
    int v; asm volatile("ld.acquire.gpu.s32 %0, [%1];" : "=r"(v) : "l"(p) : "memory");
    return v;
}
__device__ __forceinline__ void red_rel_add(int* p, int v) {
    asm volatile("red.release.gpu.global.add.s32 [%0], %1;" :: "l"(p), "r"(v) : "memory");
}
__device__ __forceinline__ void cp_async16(uint32_t s, const void* g) {
    asm volatile("cp.async.cg.shared.global [%0], [%1], 16;" :: "r"(s), "l"(g));
}
__device__ __forceinline__ void cp_async_wait_all() {
    asm volatile("cp.async.commit_group;\n\tcp.async.wait_group 0;" ::: "memory");
}
__device__ __forceinline__ void bar_arrive_named(int id, int cnt) {
    asm volatile("bar.arrive %0, %1;" :: "r"(id), "r"(cnt) : "memory");
}
__device__ __forceinline__ void bar_sync_named(int id, int cnt) {
    asm volatile("bar.sync %0, %1;" :: "r"(id), "r"(cnt) : "memory");
}
__device__ __forceinline__ float fsig(float x) {
    return 1.0f / (1.0f + __expf(-x));
}
__device__ __forceinline__ float ftanh(float x) {
    float e = __expf(-2.0f * fabsf(x));
    float r = (1.0f - e) / (1.0f + e);
    return copysignf(r, x);
}

// -------- reset (t=0 reads no g_hbuf; only the counter needs reset) ---------
__global__ void reset_kernel() {
    if (threadIdx.x == 0) g_cnt = 0;
}

// -------- dummy: shifts ncu's captured launch (#6) onto lstm_rec_kernel -----
__global__ void probe_kernel() {}

// -------- phase 1: g_xproj[r][n] = x @ [U_i|U_f|U_h|U_o] + b ---------------
__global__ void __launch_bounds__(256) xproj_kernel(
    const float* __restrict__ x,
    const float* __restrict__ Ui, const float* __restrict__ Uf,
    const float* __restrict__ Uh, const float* __restrict__ Uo,
    const float* __restrict__ bi, const float* __restrict__ bf,
    const float* __restrict__ bh, const float* __restrict__ bo)
{
    __shared__ float As[128 * 36];
    __shared__ float Bs[32 * 72];
    __shared__ float bias_s[64];

    const int tid = threadIdx.x;
    const int n0 = blockIdx.x * 64;
    const int m0 = blockIdx.y * 128;
    const int q  = n0 >> 9;
    const int c0 = n0 & 511;

    const float* Uq = (q == 0) ? Ui : (q == 1) ? Uf : (q == 2) ? Uh : Uo;
    const float* bq = (q == 0) ? bi : (q == 1) ? bf : (q == 2) ? bh : bo;
    if (tid < 64) bias_s[tid] = bq[c0 + tid];

    const int w = tid >> 5, lane = tid & 31, g = lane >> 2, tig = lane & 3;
    const int warpM = w >> 1, warpN = w & 1;

    const int arow = tid >> 1, ahalf = tid & 1;
    const int r  = m0 + arow;
    const int bbi = r & 63, tti = r >> 6;
    const float* xrow = x + ((size_t)bbi * TT + tti) * II;
    const int brow = tid >> 3, bcol8 = (tid & 7) * 8;

    float acc[2][4][4] = {};

    for (int kc = 0; kc < 8; ++kc) {
        const int k0 = kc * 32;
        #pragma unroll
        for (int i = 0; i < 4; ++i) {
            float4 v = *(const float4*)(xrow + k0 + ahalf * 16 + i * 4);
            int off = arow * 36 + ahalf * 16 + i * 4;
            As[off+0] = tf32r(v.x); As[off+1] = tf32r(v.y);
            As[off+2] = tf32r(v.z); As[off+3] = tf32r(v.w);
        }
        #pragma unroll
        for (int i = 0; i < 2; ++i) {
            float4 v = *(const float4*)(Uq + (size_t)(k0 + brow) * HH + c0 + bcol8 + i * 4);
            int off = brow * 72 + bcol8 + i * 4;
            Bs[off+0] = tf32r(v.x); Bs[off+1] = tf32r(v.y);
            Bs[off+2] = tf32r(v.z); Bs[off+3] = tf32r(v.w);
        }
        __syncthreads();

        #pragma unroll
        for (int kk = 0; kk < 32; kk += 8) {
            unsigned a[2][4];
            #pragma unroll
            for (int i2 = 0; i2 < 2; ++i2) {
                int rb = warpM * 32 + i2 * 16;
                a[i2][0] = fb(As[(rb + g    ) * 36 + kk + tig]);
                a[i2][1] = fb(As[(rb + g + 8) * 36 + kk + tig]);
                a[i2][2] = fb(As[(rb + g    ) * 36 + kk + tig + 4]);
                a[i2][3] = fb(As[(rb + g + 8) * 36 + kk + tig + 4]);
            }
            #pragma unroll
            for (int nt = 0; nt < 4; ++nt) {
                int nn = warpN * 32 + nt * 8 + g;
                unsigned b0 = fb(Bs[(kk + tig    ) * 72 + nn]);
                unsigned b1 = fb(Bs[(kk + tig + 4) * 72 + nn]);
                mma_tf32(acc[0][nt], a[0][0], a[0][1], a[0][2], a[0][3], b0, b1);
                mma_tf32(acc[1][nt], a[1][0], a[1][1], a[1][2], a[1][3], b0, b1);
            }
        }
        __syncthreads();
    }

    #pragma unroll
    for (int i2 = 0; i2 < 2; ++i2) {
        #pragma unroll
        for (int nt = 0; nt < 4; ++nt) {
            int coll = warpN * 32 + nt * 8 + 2 * tig;
            float b0v = bias_s[coll], b1v = bias_s[coll + 1];
            int row0 = m0 + warpM * 32 + i2 * 16 + g;
            *(float2*)&g_xproj[(size_t)row0 * G4 + n0 + coll] =
                make_float2(acc[i2][nt][0] + b0v, acc[i2][nt][1] + b1v);
            *(float2*)&g_xproj[(size_t)(row0 + 8) * G4 + n0 + coll] =
                make_float2(acc[i2][nt][2] + b0v, acc[i2][nt][3] + b1v);
        }
    }
}

// -------- phase 2: persistent recurrence, slim sync chain -------------------
// 8 warps = 4 M-warps x 2 K-halves; warp tile 16M x 16N x 256K, mma m16n8k16.
// Per step: per-warp spin -> per-warp stage -> bar(stage) -> MMA -> bar(gs)
// -> elementwise -> warps!=0 arrive & roll on; warp 0 syncs named bar, releases.
__global__ void __launch_bounds__(256, 1) lstm_rec_kernel(
    const float* __restrict__ Vi, const float* __restrict__ Vf,
    const float* __restrict__ Vh, const float* __restrict__ Vo)
{
    extern __shared__ char smc[];
    __half* Vt = (__half*)smc;                          // [16][520] fp16 V, [n][k]
    __half* hs = (__half*)(smc + NC * VT2 * 2);         // [64][520] staged h fp16
    float*  gs = (float*)(smc + NC * VT2 * 2 + 64 * HS2 * 2);  // [2][64][18]

    const int tid = threadIdx.x, cta = blockIdx.x;
    const int hc0 = cta * 4;
    const int w = tid >> 5, lane = tid & 31, g = lane >> 2, tig = lane & 3;
    const int mw = w & 3, ks = w >> 2;

    // load this CTA's V slice once (fp16), layout [n][k]
    {
        const float* Vq[4] = { Vi, Vf, Vh, Vo };
        for (int idx = tid; idx < NC * HH; idx += 256) {
            int n = idx >> 9, k = idx & 511;
            Vt[n * VT2 + k] = __float2half_rn(Vq[n >> 2][(size_t)k * HH + hc0 + (n & 3)]);
        }
    }
    __syncthreads();

    const int sb = tid >> 2, shc = tid & 3;        // this thread's (batch,hcol)
    const int srow = tid >> 2, sseg = tid & 3;     // staging map: 16 x 16B
    const uint32_t hs_u32 = (uint32_t)__cvta_generic_to_shared(hs);
    float c_state = 0.0f;

    const unsigned* Aw = (const unsigned*)hs + (mw * 16) * (HS2 / 2) + ks * 128;
    const unsigned* Bw = (const unsigned*)Vt + ks * 128;
    float* gsp = gs + ks * (64 * GS_S);

    for (int t = 0; t < TT; ++t) {
        // prefetch xproj (independent of h -> in flight during the spin)
        float xp[4];
        {
            const float* xb = g_xproj + ((size_t)t * BB + sb) * G4 + hc0 + shc;
            #pragma unroll
            for (int q2 = 0; q2 < 4; ++q2) xp[q2] = __ldg(xb + q2 * HH);
        }

        if (t > 0) {
            // per-warp spin: each warp wakes and stages independently
            if (lane == 0) {
                const int want = NCTA * t;
                while (ld_acq(&g_cnt) < want) { }
            }
            __syncwarp();

            // stage h_t (fp16) via cp.async: 16 x 16B per thread, coalesced
            {
                const char* hb = (const char*)(g_hbuf[t & 1] + srow * HH) + sseg * 256;
                const uint32_t hd = hs_u32 + (uint32_t)(srow * HS2 * 2 + sseg * 256);
                #pragma unroll
                for (int i = 0; i < 16; ++i)
                    cp_async16(hd + (uint32_t)(i * 16), hb + i * 16);
                cp_async_wait_all();
            }
            __syncthreads();   // barrier 1: full h tile staged

            // gates_hV partials: warp (mw,ks), 16M x 16N x 256K via m16n8k16
            {
                float acc[2][2][4] = {};   // [nt][parity][4]
                #pragma unroll
                for (int it = 0; it < 16; ++it) {
                    const int kw = it * 8;
                    const int par = it & 1;
                    unsigned a0 = Aw[(g    ) * (HS2/2) + kw + tig];
                    unsigned a1 = Aw[(g + 8) * (HS2/2) + kw + tig];
                    unsigned a2 = Aw[(g    ) * (HS2/2) + kw + 4 + tig];
                    unsigned a3 = Aw[(g + 8) * (HS2/2) + kw + 4 + tig];
                    #pragma unroll
                    for (int nt = 0; nt < 2; ++nt) {
                        unsigned b0 = Bw[(nt * 8 + g) * (VT2/2) + kw + tig];
                        unsigned b1 = Bw[(nt * 8 + g) * (VT2/2) + kw + 4 + tig];
                        mma_f16(acc[nt][par], a0, a1, a2, a3, b0, b1);
                    }
                }
                #pragma unroll
                for (int nt = 0; nt < 2; ++nt) {
                    int col = nt * 8 + 2 * tig;
                    *(float2*)&gsp[(mw * 16 + g    ) * GS_S + col] =
                        make_float2(acc[nt][0][0] + acc[nt][1][0],
                                    acc[nt][0][1] + acc[nt][1][1]);
                    *(float2*)&gsp[(mw * 16 + g + 8) * GS_S + col] =
                        make_float2(acc[nt][0][2] + acc[nt][1][2],
                                    acc[nt][0][3] + acc[nt][1][3]);
                }
            }
            __syncthreads();   // barrier 2: gate partials visible
        }

        // elementwise gate update; c in register; publish h
        {
            float gi = xp[0], gf = xp[1], gg = xp[2], go = xp[3];
            if (t > 0) {
                const float* g0 = gs + sb * GS_S + shc;
                const float* g1 = g0 + 64 * GS_S;
                gi += g0[0]  + g1[0];
                gf += g0[4]  + g1[4];
                gg += g0[8]  + g1[8];
                go += g0[12] + g1[12];
            }
            float it = fsig(gi), ft = fsig(gf), ot = fsig(go);
            c_state = ft * c_state + it * ftanh(gg);
            g_hbuf[(t + 1) & 1][sb * HH + hc0 + shc] =
                __float2half_rn(ot * ftanh(c_state));
        }

        // split end-of-step barrier: warp 0 gathers arrivals then releases;
        // warps 1..7 roll straight into the next iteration (prefetch + spin).
        if (w == 0) {
            bar_sync_named(1, 256);
            if (lane == 0) red_rel_add(&g_cnt, 1);
        } else {
            bar_arrive_named(1, 256);
        }
    }
}

// -------- phase 3: out[b] = h_last . fc_w + fc_b ----------------------------
__global__ void fc_kernel(const float* __restrict__ fc_w,
                          const float* __restrict__ fc_b, float* out) {
    int b = blockIdx.x, tid = threadIdx.x;
    const __half* h = g_hbuf[0] + b * HH;  // h_1024 in buf[(1023+1)&1] = buf[0]
    float s = 0.0f;
    for (int k = tid; k < HH; k += 128) s += __half2float(h[k]) * fc_w[k];
    #pragma unroll
    for (int o = 16; o; o >>= 1) s += __shfl_down_sync(0xFFFFFFFFu, s, o);
    __shared__ float ws[4];
    if ((tid & 31) == 0) ws[tid >> 5] = s;
    __syncthreads();
    if (tid == 0) out[b] = ws[0] + ws[1] + ws[2] + ws[3] + fc_b[0];
}

// -------- launch -------------------------------------------------------------
extern "C" void kernel_launch(void* const* d_in, const int* in_sizes, int n_in,
                              void* d_out, int out_size) {
    const float* x   = (const float*)d_in[0];
    const float* Ui  = (const float*)d_in[1];
    const float* Vi  = (const float*)d_in[2];
    const float* bi  = (const float*)d_in[3];
    const float* Uf  = (const float*)d_in[4];
    const float* Vf  = (const float*)d_in[5];
    const float* bf  = (const float*)d_in[6];
    const float* Uh  = (const float*)d_in[7];
    const float* Vh  = (const float*)d_in[8];
    const float* bh  = (const float*)d_in[9];
    const float* Uo  = (const float*)d_in[10];
    const float* Vo  = (const float*)d_in[11];
    const float* bo  = (const float*)d_in[12];
    const float* fcw = (const float*)d_in[13];
    const float* fcb = (const float*)d_in[14];
    float* out = (float*)d_out;

    cudaFuncSetAttribute(lstm_rec_kernel,
                         cudaFuncAttributeMaxDynamicSharedMemorySize, REC_SMEM_BYTES);

    reset_kernel<<<1, 32>>>();
    dim3 gx(G4 / 64, (BB * TT) / 128);
    xproj_kernel<<<gx, 256>>>(x, Ui, Uf, Uh, Uo, bi, bf, bh, bo);
    probe_kernel<<<1, 32>>>();   // keeps ncu capture (-s 5 -c 1) on rec kernel
    lstm_rec_kernel<<<NCTA, 256, REC_SMEM_BYTES>>>(Vi, Vf, Vh, Vo);
    fc_kernel<<<BB, 128>>>(fcw, fcb, out);
}

// round 14
// speedup vs baseline: 1.8174x; 1.8174x over previous
#include <cuda_runtime.h>
#include <cuda_fp16.h>
#include <cstdint>

#define BB 64
#define TT 1024
#define II 256
#define HH 512
#define G4 2048
#define NCTA 128          // 4 groups x 32 CTAs; group g owns batches [16g,16g+16)
#define GRP_SH 5          // 32 CTAs per group
#define NB 16             // batches per group
#define NHID 16           // hidden dims per CTA
#define NCOLS 64          // gate cols per CTA (16 hid x 4 gates)
#define VT2 520           // V smem stride in halves (word stride 260 == 4 mod 32)
#define HS2 520           // h smem stride in halves
#define GSF 68            // gate-exchange stride in floats (== 4 mod 32)
#define REC_SMEM_BYTES 120000   // 100,608 used; padded so exactly 1 CTA/SM

// -------- global scratch (static device memory; no runtime allocation) -----
__device__ float  g_xproj[(size_t)BB * TT * G4];  // [t*64+b][2048], bias folded
__device__ __half g_hbuf[2][BB * HH];             // [grp][16][512] halves, ping-pong
__device__ int    g_cnt4[4 * 32];                 // per-group counters, 128B apart

// -------- helpers -----------------------------------------------------------
__device__ __forceinline__ float tf32r(float f) {
    unsigned u; asm("cvt.rna.tf32.f32 %0, %1;" : "=r"(u) : "f"(f));
    return __uint_as_float(u);
}
__device__ __forceinline__ unsigned fb(float f) { return __float_as_uint(f); }

__device__ __forceinline__ void mma_tf32(float* c,
    unsigned a0, unsigned a1, unsigned a2, unsigned a3, unsigned b0, unsigned b1) {
    asm volatile(
        "mma.sync.aligned.m16n8k8.row.col.f32.tf32.tf32.f32 "
        "{%0,%1,%2,%3},{%4,%5,%6,%7},{%8,%9},{%0,%1,%2,%3};"
        : "+f"(c[0]), "+f"(c[1]), "+f"(c[2]), "+f"(c[3])
        : "r"(a0), "r"(a1), "r"(a2), "r"(a3), "r"(b0), "r"(b1));
}
__device__ __forceinline__ void mma_f16(float* c,
    unsigned a0, unsigned a1, unsigned a2, unsigned a3, unsigned b0, unsigned b1) {
    asm volatile(
        "mma.sync.aligned.m16n8k16.row.col.f32.f16.f16.f32 "
        "{%0,%1,%2,%3},{%4,%5,%6,%7},{%8,%9},{%0,%1,%2,%3};"
        : "+f"(c[0]), "+f"(c[1]), "+f"(c[2]), "+f"(c[3])
        : "r"(a0), "r"(a1), "r"(a2), "r"(a3), "r"(b0), "r"(b1));
}
__device__ __forceinline__ int ld_acq(const int* p) {
    int v; asm volatile("ld.acquire.gpu.s32 %0, [%1];" : "=r"(v) : "l"(p) : "memory");
    return v;
}
__device__ __forceinline__ void red_rel_add(int* p, int v) {
    asm volatile("red.release.gpu.global.add.s32 [%0], %1;" :: "l"(p), "r"(v) : "memory");
}
__device__ __forceinline__ void cp_async16(uint32_t s, const void* g) {
    asm volatile("cp.async.cg.shared.global [%0], [%1], 16;" :: "r"(s), "l"(g));
}
__device__ __forceinline__ void cp_async_wait_all() {
    asm volatile("cp.async.commit_group;\n\tcp.async.wait_group 0;" ::: "memory");
}
__device__ __forceinline__ float fsig(float x) {
    return 1.0f / (1.0f + __expf(-x));
}
__device__ __forceinline__ float ftanh(float x) {
    float e = __expf(-2.0f * fabsf(x));
    float r = (1.0f - e) / (1.0f + e);
    return copysignf(r, x);
}

// -------- reset (t=0 reads no g_hbuf; only counters need reset) -------------
__global__ void reset_kernel() {
    if (threadIdx.x < 4) g_cnt4[threadIdx.x * 32] = 0;
}

// -------- dummy: shifts ncu's captured launch (#6) onto lstm_rec_kernel -----
__global__ void probe_kernel() {}

// -------- phase 1: g_xproj[r][n] = x @ [U_i|U_f|U_h|U_o] + b ---------------
__global__ void __launch_bounds__(256) xproj_kernel(
    const float* __restrict__ x,
    const float* __restrict__ Ui, const float* __restrict__ Uf,
    const float* __restrict__ Uh, const float* __restrict__ Uo,
    const float* __restrict__ bi, const float* __restrict__ bf,
    const float* __restrict__ bh, const float* __restrict__ bo)
{
    __shared__ float As[128 * 36];
    __shared__ float Bs[32 * 72];
    __shared__ float bias_s[64];

    const int tid = threadIdx.x;
    const int n0 = blockIdx.x * 64;
    const int m0 = blockIdx.y * 128;
    const int q  = n0 >> 9;
    const int c0 = n0 & 511;

    const float* Uq = (q == 0) ? Ui : (q == 1) ? Uf : (q == 2) ? Uh : Uo;
    const float* bq = (q == 0) ? bi : (q == 1) ? bf : (q == 2) ? bh : bo;
    if (tid < 64) bias_s[tid] = bq[c0 + tid];

    const int w = tid >> 5, lane = tid & 31, g = lane >> 2, tig = lane & 3;
    const int warpM = w >> 1, warpN = w & 1;

    const int arow = tid >> 1, ahalf = tid & 1;
    const int r  = m0 + arow;
    const int bbi = r & 63, tti = r >> 6;
    const float* xrow = x + ((size_t)bbi * TT + tti) * II;
    const int brow = tid >> 3, bcol8 = (tid & 7) * 8;

    float acc[2][4][4] = {};

    for (int kc = 0; kc < 8; ++kc) {
        const int k0 = kc * 32;
        #pragma unroll
        for (int i = 0; i < 4; ++i) {
            float4 v = *(const float4*)(xrow + k0 + ahalf * 16 + i * 4);
            int off = arow * 36 + ahalf * 16 + i * 4;
            As[off+0] = tf32r(v.x); As[off+1] = tf32r(v.y);
            As[off+2] = tf32r(v.z); As[off+3] = tf32r(v.w);
        }
        #pragma unroll
        for (int i = 0; i < 2; ++i) {
            float4 v = *(const float4*)(Uq + (size_t)(k0 + brow) * HH + c0 + bcol8 + i * 4);
            int off = brow * 72 + bcol8 + i * 4;
            Bs[off+0] = tf32r(v.x); Bs[off+1] = tf32r(v.y);
            Bs[off+2] = tf32r(v.z); Bs[off+3] = tf32r(v.w);
        }
        __syncthreads();

        #pragma unroll
        for (int kk = 0; kk < 32; kk += 8) {
            unsigned a[2][4];
            #pragma unroll
            for (int i2 = 0; i2 < 2; ++i2) {
                int rb = warpM * 32 + i2 * 16;
                a[i2][0] = fb(As[(rb + g    ) * 36 + kk + tig]);
                a[i2][1] = fb(As[(rb + g + 8) * 36 + kk + tig]);
                a[i2][2] = fb(As[(rb + g    ) * 36 + kk + tig + 4]);
                a[i2][3] = fb(As[(rb + g + 8) * 36 + kk + tig + 4]);
            }
            #pragma unroll
            for (int nt = 0; nt < 4; ++nt) {
                int nn = warpN * 32 + nt * 8 + g;
                unsigned b0 = fb(Bs[(kk + tig    ) * 72 + nn]);
                unsigned b1 = fb(Bs[(kk + tig + 4) * 72 + nn]);
                mma_tf32(acc[0][nt], a[0][0], a[0][1], a[0][2], a[0][3], b0, b1);
                mma_tf32(acc[1][nt], a[1][0], a[1][1], a[1][2], a[1][3], b0, b1);
            }
        }
        __syncthreads();
    }

    #pragma unroll
    for (int i2 = 0; i2 < 2; ++i2) {
        #pragma unroll
        for (int nt = 0; nt < 4; ++nt) {
            int coll = warpN * 32 + nt * 8 + 2 * tig;
            float b0v = bias_s[coll], b1v = bias_s[coll + 1];
            int row0 = m0 + warpM * 32 + i2 * 16 + g;
            *(float2*)&g_xproj[(size_t)row0 * G4 + n0 + coll] =
                make_float2(acc[i2][nt][0] + b0v, acc[i2][nt][1] + b1v);
            *(float2*)&g_xproj[(size_t)(row0 + 8) * G4 + n0 + coll] =
                make_float2(acc[i2][nt][2] + b0v, acc[i2][nt][3] + b1v);
        }
    }
}

// -------- phase 2: persistent recurrence, 4 independent batch groups --------
// Group = 16 batches x 32 CTAs. CTA owns 16 hidden dims (64 gate cols).
// MMA per CTA: m16(batch) x n64 x k512, 8 warps = 2 N-halves x 4 K-quarters.
// Per-group counter barrier (fan-in 32), R7-proven sync chain.
__global__ void __launch_bounds__(256, 1) lstm_rec_kernel(
    const float* __restrict__ Vi, const float* __restrict__ Vf,
    const float* __restrict__ Vh, const float* __restrict__ Vo)
{
    extern __shared__ char smc[];
    __half* Vt = (__half*)smc;                          // [64][520] fp16 V, [n][k]
    __half* hs = (__half*)(smc + NCOLS * VT2 * 2);      // [16][520] staged h fp16
    float*  gs = (float*)(smc + NCOLS * VT2 * 2 + NB * HS2 * 2); // [4][16][68]

    const int tid = threadIdx.x, cta = blockIdx.x;
    const int grp = cta >> GRP_SH, cig = cta & 31;
    const int hc0 = cig * NHID;                 // hidden base within group
    const int w = tid >> 5, lane = tid & 31, g = lane >> 2, tig = lane & 3;
    const int nh = w & 1, kq = w >> 1;
    int* gcnt = &g_cnt4[grp * 32];

    // load this CTA's V slice once (fp16), layout [n][k], n = gate*16 + hid
    {
        const float* Vq[4] = { Vi, Vf, Vh, Vo };
        for (int idx = tid; idx < NCOLS * HH; idx += 256) {
            int n = idx >> 9, k = idx & 511;
            Vt[n * VT2 + k] = __float2half_rn(Vq[n >> 4][(size_t)k * HH + hc0 + (n & 15)]);
        }
    }
    __syncthreads();

    const int bb = tid >> 4, hh = tid & 15;     // this thread's (batch, hidden)
    const int srow = tid >> 4, sseg = tid & 15; // staging: 4 x 16B per thread
    const uint32_t hs_u32 = (uint32_t)__cvta_generic_to_shared(hs);
    float c_state = 0.0f;

    const unsigned* Aw = (const unsigned*)hs + kq * 64;
    const unsigned* Bw = (const unsigned*)Vt + (nh * 32) * (VT2 / 2) + kq * 64;
    float* gsp = gs + kq * (NB * GSF);
    const int gbase = grp * (NB * HH);          // group offset in g_hbuf halves

    for (int t = 0; t < TT; ++t) {
        // prefetch xproj (independent of h -> in flight during the spin)
        float xp[4];
        {
            const float* xb = g_xproj + ((size_t)t * BB + grp * NB + bb) * G4 + hc0 + hh;
            #pragma unroll
            for (int q2 = 0; q2 < 4; ++q2) xp[q2] = __ldg(xb + q2 * HH);
        }

        if (t > 0) {
            // wait for this group's 32 CTAs to have published h_t
            if (tid == 0) {
                const int want = 32 * t;
                while (ld_acq(gcnt) < want) { }
            }
            __syncthreads();

            // stage group h_t (16KB) via cp.async: 4 x 16B per thread
            {
                const char* hb = (const char*)(g_hbuf[t & 1] + gbase + srow * HH)
                                 + sseg * 64;
                const uint32_t hd = hs_u32 + (uint32_t)(srow * HS2 * 2 + sseg * 64);
                #pragma unroll
                for (int i = 0; i < 4; ++i)
                    cp_async16(hd + (uint32_t)(i * 16), hb + i * 16);
                cp_async_wait_all();
            }
            __syncthreads();   // barrier 1: h tile staged

            // gates_hV partials: warp (nh,kq), m16 x n32 x k128 via m16n8k16
            {
                float acc[4][2][4] = {};   // [nt][parity][4]
                #pragma unroll
                for (int it = 0; it < 8; ++it) {
                    const int kw = it * 8;
                    const int par = it & 1;
                    unsigned a0 = Aw[(g    ) * (HS2/2) + kw + tig];
                    unsigned a1 = Aw[(g + 8) * (HS2/2) + kw + tig];
                    unsigned a2 = Aw[(g    ) * (HS2/2) + kw + 4 + tig];
                    unsigned a3 = Aw[(g + 8) * (HS2/2) + kw + 4 + tig];
                    #pragma unroll
                    for (int nt = 0; nt < 4; ++nt) {
                        unsigned b0 = Bw[(nt * 8 + g) * (VT2/2) + kw + tig];
                        unsigned b1 = Bw[(nt * 8 + g) * (VT2/2) + kw + 4 + tig];
                        mma_f16(acc[nt][par], a0, a1, a2, a3, b0, b1);
                    }
                }
                #pragma unroll
                for (int nt = 0; nt < 4; ++nt) {
                    int col = nh * 32 + nt * 8 + 2 * tig;
                    *(float2*)&gsp[(g    ) * GSF + col] =
                        make_float2(acc[nt][0][0] + acc[nt][1][0],
                                    acc[nt][0][1] + acc[nt][1][1]);
                    *(float2*)&gsp[(g + 8) * GSF + col] =
                        make_float2(acc[nt][0][2] + acc[nt][1][2],
                                    acc[nt][0][3] + acc[nt][1][3]);
                }
            }
            __syncthreads();   // barrier 2: gate partials visible
        }

        // elementwise gate update; c in register; publish h (fp16)
        {
            float gi = xp[0], gf = xp[1], gg = xp[2], go = xp[3];
            if (t > 0) {
                const float* gb = gs + bb * GSF + hh;
                #pragma unroll
                for (int p = 0; p < 4; ++p) {
                    const float* gp = gb + p * (NB * GSF);
                    gi += gp[0]; gf += gp[16]; gg += gp[32]; go += gp[48];
                }
            }
            float it = fsig(gi), ft = fsig(gf), ot = fsig(go);
            c_state = ft * c_state + it * ftanh(gg);
            g_hbuf[(t + 1) & 1][gbase + bb * HH + hc0 + hh] =
                __float2half_rn(ot * ftanh(c_state));
        }
        __syncthreads();
        if (tid == 0) red_rel_add(gcnt, 1);
    }
}

// -------- phase 3: out[b] = h_last . fc_w + fc_b ----------------------------
__global__ void fc_kernel(const float* __restrict__ fc_w,
                          const float* __restrict__ fc_b, float* out) {
    int b = blockIdx.x, tid = threadIdx.x;
    // h_1024 in buf[(1023+1)&1] = buf[0]; layout [grp][16][512]
    const __half* h = g_hbuf[0] + (b >> 4) * (NB * HH) + (b & 15) * HH;
    float s = 0.0f;
    for (int k = tid; k < HH; k += 128) s += __half2float(h[k]) * fc_w[k];
    #pragma unroll
    for (int o = 16; o; o >>= 1) s += __shfl_down_sync(0xFFFFFFFFu, s, o);
    __shared__ float ws[4];
    if ((tid & 31) == 0) ws[tid >> 5] = s;
    __syncthreads();
    if (tid == 0) out[b] = ws[0] + ws[1] + ws[2] + ws[3] + fc_b[0];
}

// -------- launch -------------------------------------------------------------
extern "C" void kernel_launch(void* const* d_in, const int* in_sizes, int n_in,
                              void* d_out, int out_size) {
    const float* x   = (const float*)d_in[0];
    const float* Ui  = (const float*)d_in[1];
    const float* Vi  = (const float*)d_in[2];
    const float* bi  = (const float*)d_in[3];
    const float* Uf  = (const float*)d_in[4];
    const float* Vf  = (const float*)d_in[5];
    const float* bf  = (const float*)d_in[6];
    const float* Uh  = (const float*)d_in[7];
    const float* Vh  = (const float*)d_in[8];
    const float* bh  = (const float*)d_in[9];
    const float* Uo  = (const float*)d_in[10];
    const float* Vo  = (const float*)d_in[11];
    const float* bo  = (const float*)d_in[12];
    const float* fcw = (const float*)d_in[13];
    const float* fcb = (const float*)d_in[14];
    float* out = (float*)d_out;

    cudaFuncSetAttribute(lstm_rec_kernel,
                         cudaFuncAttributeMaxDynamicSharedMemorySize, REC_SMEM_BYTES);

    reset_kernel<<<1, 32>>>();
    dim3 gx(G4 / 64, (BB * TT) / 128);
    xproj_kernel<<<gx, 256>>>(x, Ui, Uf, Uh, Uo, bi, bf, bh, bo);
    probe_kernel<<<1, 32>>>();   // keeps ncu capture (-s 5 -c 1) on rec kernel
    lstm_rec_kernel<<<NCTA, 256, REC_SMEM_BYTES>>>(Vi, Vf, Vh, Vo);
    fc_kernel<<<BB, 128>>>(fcw, fcb, out);
}